// round 11
// baseline (speedup 1.0000x reference)
#include <cuda_runtime.h>
#include <cuda_bf16.h>
#include <math_constants.h>
#include <cstdint>

// Problem constants
#define B   4
#define S   2048
#define NX  1024
#define H   16
#define D   64
#define M_TOT (B * S)   // 8192

// Scratch
__device__ float g_qkv[(size_t)M_TOT * 3 * NX];   // (8192, 3072)
__device__ float g_ctx[(size_t)M_TOT * NX];       // (8192, 1024) tf32-rounded
__device__ float g_xc[(size_t)M_TOT * NX];        // x, tf32-rounded
__device__ float g_wt1[(size_t)3 * NX * NX];      // c_attn_w^T, tf32
__device__ float g_wt2[(size_t)NX * NX];          // c_proj_w^T, tf32
__device__ float g_kc[(size_t)64 * S * D];        // K tf32, [bh][s][d-pperm]
__device__ float g_vt[(size_t)64 * D * S];        // V tf32, [bh][d][s]

// ---------------------------------------------------------------------------
// Helpers
// ---------------------------------------------------------------------------
__device__ __forceinline__ uint32_t f2tf32(float x) {
    uint32_t u;
    asm("cvt.rna.tf32.f32 %0, %1;" : "=r"(u) : "f"(x));
    return u;
}
__device__ __forceinline__ float f2tf32f(float x) {
    return __uint_as_float(f2tf32(x));
}

// mma.sync m16n8k8 tf32: D = A*B + D (fp32 accum)
__device__ __forceinline__ void mma8(float* c, const uint32_t* a,
                                     uint32_t b0, uint32_t b1) {
    asm volatile(
        "mma.sync.aligned.m16n8k8.row.col.f32.tf32.tf32.f32 "
        "{%0,%1,%2,%3}, {%4,%5,%6,%7}, {%8,%9}, {%0,%1,%2,%3};"
        : "+f"(c[0]), "+f"(c[1]), "+f"(c[2]), "+f"(c[3])
        : "r"(a[0]), "r"(a[1]), "r"(a[2]), "r"(a[3]), "r"(b0), "r"(b1));
}

// ---------------------------------------------------------------------------
// tf32-convert x
// ---------------------------------------------------------------------------
__global__ void cvt_tf32(const float* __restrict__ in, float* __restrict__ out)
{
    const int i = blockIdx.x * 256 + threadIdx.x;
    float4 v = *(const float4*)(in + (size_t)i * 4);
    v.x = f2tf32f(v.x); v.y = f2tf32f(v.y);
    v.z = f2tf32f(v.z); v.w = f2tf32f(v.w);
    *(float4*)(out + (size_t)i * 4) = v;
}

// ---------------------------------------------------------------------------
// Weight transpose + tf32 convert: Wt[n][k] = tf32(W[k][n])
// ---------------------------------------------------------------------------
__global__ void transpose_cvt(const float* __restrict__ W, float* __restrict__ Wt,
                              int K, int N)
{
    __shared__ float t[32][33];
    const int k0 = blockIdx.y * 32, n0 = blockIdx.x * 32;
    const int x = threadIdx.x, y = threadIdx.y;   // 32 x 8
#pragma unroll
    for (int i = 0; i < 32; i += 8)
        t[y + i][x] = W[(size_t)(k0 + y + i) * N + n0 + x];
    __syncthreads();
#pragma unroll
    for (int i = 0; i < 32; i += 8)
        Wt[(size_t)(n0 + y + i) * K + k0 + x] = f2tf32f(t[x][y + i]);
}

// ---------------------------------------------------------------------------
// Prep K/V: tf32; K d-axis pair-permuted; V transposed, keys unpermuted.
// ---------------------------------------------------------------------------
__global__ __launch_bounds__(256)
void prep_kv(const float* __restrict__ qkv, float* __restrict__ kc,
             float* __restrict__ vt)
{
    __shared__ float vs[64][65];
    const int bh = blockIdx.y;
    const int b = bh >> 4, h = bh & 15;
    const int s0 = blockIdx.x * 64;
    const int tid = threadIdx.x;

    const float* kbase = qkv + (size_t)b * S * (3 * NX) + NX + h * D;
    const float* vbase = qkv + (size_t)b * S * (3 * NX) + 2 * NX + h * D;

    for (int idx = tid; idx < 64 * 16; idx += 256) {
        const int r  = idx >> 4;
        const int ve = idx & 15;
        const size_t grow = (size_t)(s0 + r) * (3 * NX) + ve * 4;
        float4 kv = *(const float4*)(kbase + grow);
        float* out = kc + ((size_t)bh * S + s0 + r) * D + (ve >> 1) * 8 + (ve & 1);
        out[0] = f2tf32f(kv.x);
        out[2] = f2tf32f(kv.y);
        out[4] = f2tf32f(kv.z);
        out[6] = f2tf32f(kv.w);
        float4 vv = *(const float4*)(vbase + grow);
        vs[4 * ve + 0][r] = vv.x;
        vs[4 * ve + 1][r] = vv.y;
        vs[4 * ve + 2][r] = vv.z;
        vs[4 * ve + 3][r] = vv.w;
    }
    __syncthreads();

    for (int idx = tid; idx < 64 * 16; idx += 256) {
        const int d  = idx >> 4;
        const int ve = idx & 15;
        const int pb = ve * 4;
        float4 ov;
        ov.x = f2tf32f(vs[d][pb + 0]);
        ov.y = f2tf32f(vs[d][pb + 1]);
        ov.z = f2tf32f(vs[d][pb + 2]);
        ov.w = f2tf32f(vs[d][pb + 3]);
        *(float4*)(vt + ((size_t)bh * D + d) * S + s0 + pb) = ov;
    }
}

// ---------------------------------------------------------------------------
// tf32 mma GEMM, smem double-buffer + register prefetch, 1 sync per tile:
// C[M,N] = A[M,K] @ Bt[N,K]^T + bias[N]
// Block 128x128, K-tile 32, 256 threads, warp tile 64x32.
// ---------------------------------------------------------------------------
#define GLD 36

__global__ __launch_bounds__(256)
void gemm_mma(const float* __restrict__ A, const float* __restrict__ Bt,
              const float* __restrict__ bias, float* __restrict__ C,
              int M, int N, int K)
{
    extern __shared__ float gsm[];
    float* Abuf[2] = {gsm,                gsm + 2 * 128 * GLD};
    float* Bbuf[2] = {gsm + 128 * GLD,    gsm + 3 * 128 * GLD};

    const int tid  = threadIdx.x;
    const int wid  = tid >> 5;
    const int lane = tid & 31;
    const int g    = lane >> 2;
    const int tig  = lane & 3;

    const int brow = blockIdx.y * 128;
    const int bcol = blockIdx.x * 128;
    const int wm = (wid >> 2) * 64;
    const int wn = (wid & 3) * 32;

    // Per-thread load mapping: rows r0+32i (i=0..3), float4 column ve
    const int r0 = tid >> 3;            // 0..31
    const int ve = tid & 7;             // 0..7
    const float* Arow = A  + (size_t)(brow + r0) * K + ve * 4;
    const float* Brow = Bt + (size_t)(bcol + r0) * K + ve * 4;

    float c[4][4][4];
#pragma unroll
    for (int mi = 0; mi < 4; mi++)
#pragma unroll
        for (int ni = 0; ni < 4; ni++)
#pragma unroll
            for (int j = 0; j < 4; j++) c[mi][ni][j] = 0.f;

    const int KT = K / 32;
    float4 pa[4], pb[4];

    // Prologue: load tile 0, store to buffer 0
#pragma unroll
    for (int i = 0; i < 4; i++) {
        pa[i] = *(const float4*)(Arow + (size_t)(32 * i) * K);
        pb[i] = *(const float4*)(Brow + (size_t)(32 * i) * K);
    }
#pragma unroll
    for (int i = 0; i < 4; i++) {
        *(float4*)&Abuf[0][(r0 + 32 * i) * GLD + ve * 4] = pa[i];
        *(float4*)&Bbuf[0][(r0 + 32 * i) * GLD + ve * 4] = pb[i];
    }

    for (int kc = 0; kc < KT; kc++) {
        __syncthreads();   // buffer kc&1 fully written

        // Prefetch next tile into registers (overlaps compute)
        if (kc + 1 < KT) {
            const int k0 = (kc + 1) * 32;
#pragma unroll
            for (int i = 0; i < 4; i++) {
                pa[i] = *(const float4*)(Arow + (size_t)(32 * i) * K + k0);
                pb[i] = *(const float4*)(Brow + (size_t)(32 * i) * K + k0);
            }
        }

        const float* Ab = Abuf[kc & 1];
        const float* Bb = Bbuf[kc & 1];

#pragma unroll
        for (int ks = 0; ks < 4; ks++) {
            const int kk = ks * 8;
            uint32_t af[4][4], bf[4][2];
#pragma unroll
            for (int mi = 0; mi < 4; mi++) {
                const int r = wm + mi * 16;
                af[mi][0] = __float_as_uint(Ab[(r + g) * GLD + kk + tig]);
                af[mi][1] = __float_as_uint(Ab[(r + g + 8) * GLD + kk + tig]);
                af[mi][2] = __float_as_uint(Ab[(r + g) * GLD + kk + tig + 4]);
                af[mi][3] = __float_as_uint(Ab[(r + g + 8) * GLD + kk + tig + 4]);
            }
#pragma unroll
            for (int ni = 0; ni < 4; ni++) {
                const int r = wn + ni * 8;
                bf[ni][0] = __float_as_uint(Bb[(r + g) * GLD + kk + tig]);
                bf[ni][1] = __float_as_uint(Bb[(r + g) * GLD + kk + tig + 4]);
            }
#pragma unroll
            for (int mi = 0; mi < 4; mi++)
#pragma unroll
                for (int ni = 0; ni < 4; ni++)
                    mma8(c[mi][ni], af[mi], bf[ni][0], bf[ni][1]);
        }

        // Store prefetched tile into the other buffer
        if (kc + 1 < KT) {
            float* An = Abuf[(kc + 1) & 1];
            float* Bn = Bbuf[(kc + 1) & 1];
#pragma unroll
            for (int i = 0; i < 4; i++) {
                *(float4*)&An[(r0 + 32 * i) * GLD + ve * 4] = pa[i];
                *(float4*)&Bn[(r0 + 32 * i) * GLD + ve * 4] = pb[i];
            }
        }
    }

#pragma unroll
    for (int mi = 0; mi < 4; mi++) {
        const int row0 = brow + wm + mi * 16 + g;
#pragma unroll
        for (int ni = 0; ni < 4; ni++) {
            const int col = bcol + wn + ni * 8 + 2 * tig;
            float2 bb = *(const float2*)(bias + col);
            float2 v0, v1;
            v0.x = c[mi][ni][0] + bb.x; v0.y = c[mi][ni][1] + bb.y;
            v1.x = c[mi][ni][2] + bb.x; v1.y = c[mi][ni][3] + bb.y;
            *(float2*)(C + (size_t)row0 * N + col) = v0;
            *(float2*)(C + (size_t)(row0 + 8) * N + col) = v1;
        }
    }
}

// ---------------------------------------------------------------------------
// Flash attention: 8 warps, TQ=128, TK=64, 2 CTAs/SM (16 warps/SM).
// Copy-only K/V staging amortized over 8 warps. P stays in registers
// (af = tf32{c0, c2, c1, c3}); V keys unpermuted.
// ---------------------------------------------------------------------------
#define KP 72
#define PP 68

__global__ void __launch_bounds__(256, 2)
flash_attn_mma(const float* __restrict__ qkv, const float* __restrict__ kc,
               const float* __restrict__ vt, const float* __restrict__ mask,
               float* __restrict__ ctx)
{
    extern __shared__ float sm[];
    float* Qs = sm;                    // [128][PP]  Q staging
    float* Ks = Qs + 128 * PP;         // [64][KP]   (key, d-pperm)
    float* Vt = Ks + 64 * KP;          // [64][KP]   (d, key)
    float* mk = Vt + 64 * KP;          // [64]

    const int bh = blockIdx.y;
    const int b  = bh >> 4;
    const int h  = bh & 15;
    const int q0 = blockIdx.x * 128;

    const int tid  = threadIdx.x;
    const int wid  = tid >> 5;
    const int lane = tid & 31;
    const int g    = lane >> 2;
    const int tig  = lane & 3;
    const int m0   = wid * 16;

    const float* qptr = qkv + (size_t)b * S * (3 * NX) + (size_t)h * D;
    for (int idx = tid; idx < 128 * 16; idx += 256) {
        const int r  = idx >> 4;
        const int ve = idx & 15;
        float4 qa = *(const float4*)(qptr + (size_t)(q0 + r) * (3 * NX) + ve * 4);
        float* dst = &Qs[r * PP + ve * 4];
        dst[0] = f2tf32f(qa.x);
        dst[1] = f2tf32f(qa.y);
        dst[2] = f2tf32f(qa.z);
        dst[3] = f2tf32f(qa.w);
    }
    __syncthreads();

    uint32_t aq[8][4];
#pragma unroll
    for (int ks = 0; ks < 8; ks++) {
        const int kk = ks * 8;
        aq[ks][0] = __float_as_uint(Qs[(m0 + g) * PP + kk + tig]);
        aq[ks][1] = __float_as_uint(Qs[(m0 + g + 8) * PP + kk + tig]);
        aq[ks][2] = __float_as_uint(Qs[(m0 + g) * PP + kk + tig + 4]);
        aq[ks][3] = __float_as_uint(Qs[(m0 + g + 8) * PP + kk + tig + 4]);
    }

    float mi0 = -CUDART_INF_F, mi1 = -CUDART_INF_F;
    float li0 = 0.f, li1 = 0.f;
    float o[8][4];
#pragma unroll
    for (int ni = 0; ni < 8; ni++)
#pragma unroll
        for (int j = 0; j < 4; j++) o[ni][j] = 0.f;

    const float* kcb = kc + (size_t)bh * S * D;
    const float* vtb = vt + (size_t)bh * D * S;

    for (int kt = 0; kt < S / 64; kt++) {
        const int k0g = kt * 64;
        __syncthreads();

        for (int idx = tid; idx < 64 * 16; idx += 256) {
            const int r  = idx >> 4;
            const int ve = idx & 15;
            float4 kv = *(const float4*)(kcb + (size_t)(k0g + r) * D + ve * 4);
            *(float4*)&Ks[r * KP + ve * 4] = kv;
            float4 vv = *(const float4*)(vtb + (size_t)r * S + k0g + ve * 4);
            *(float4*)&Vt[r * KP + ve * 4] = vv;
        }
        if (tid < 16)
            *(float4*)&mk[tid * 4] = *(const float4*)&mask[(size_t)b * S + k0g + tid * 4];
        __syncthreads();

        // ---- QK^T
        float c[8][4];
#pragma unroll
        for (int ni = 0; ni < 8; ni++)
#pragma unroll
            for (int j = 0; j < 4; j++) c[ni][j] = 0.f;

#pragma unroll
        for (int ks = 0; ks < 8; ks++) {
            const int kk = ks * 8 + 2 * tig;
            uint32_t bf[8][2];
#pragma unroll
            for (int ni = 0; ni < 8; ni++) {
                float2 bb = *(const float2*)&Ks[(ni * 8 + g) * KP + kk];
                bf[ni][0] = __float_as_uint(bb.x);
                bf[ni][1] = __float_as_uint(bb.y);
            }
#pragma unroll
            for (int ni = 0; ni < 8; ni++)
                mma8(c[ni], aq[ks], bf[ni][0], bf[ni][1]);
        }

        // ---- scale + mask
#pragma unroll
        for (int ni = 0; ni < 8; ni++) {
            float2 mm = *(const float2*)&mk[ni * 8 + 2 * tig];
            c[ni][0] = fmaf(c[ni][0], 0.125f, mm.x);
            c[ni][1] = fmaf(c[ni][1], 0.125f, mm.y);
            c[ni][2] = fmaf(c[ni][2], 0.125f, mm.x);
            c[ni][3] = fmaf(c[ni][3], 0.125f, mm.y);
        }

        // ---- online softmax
        float mt0 = -CUDART_INF_F, mt1 = -CUDART_INF_F;
#pragma unroll
        for (int ni = 0; ni < 8; ni++) {
            mt0 = fmaxf(mt0, fmaxf(c[ni][0], c[ni][1]));
            mt1 = fmaxf(mt1, fmaxf(c[ni][2], c[ni][3]));
        }
        mt0 = fmaxf(mt0, __shfl_xor_sync(0xffffffffu, mt0, 1));
        mt0 = fmaxf(mt0, __shfl_xor_sync(0xffffffffu, mt0, 2));
        mt1 = fmaxf(mt1, __shfl_xor_sync(0xffffffffu, mt1, 1));
        mt1 = fmaxf(mt1, __shfl_xor_sync(0xffffffffu, mt1, 2));

        const float mn0 = fmaxf(mi0, mt0);
        const float mn1 = fmaxf(mi1, mt1);
        const float fac0 = __expf(mi0 - mn0);
        const float fac1 = __expf(mi1 - mn1);
        mi0 = mn0; mi1 = mn1;

        float lt0 = 0.f, lt1 = 0.f;
#pragma unroll
        for (int ni = 0; ni < 8; ni++) {
            c[ni][0] = __expf(c[ni][0] - mn0);
            c[ni][1] = __expf(c[ni][1] - mn0);
            c[ni][2] = __expf(c[ni][2] - mn1);
            c[ni][3] = __expf(c[ni][3] - mn1);
            lt0 += c[ni][0] + c[ni][1];
            lt1 += c[ni][2] + c[ni][3];
        }
        lt0 += __shfl_xor_sync(0xffffffffu, lt0, 1);
        lt0 += __shfl_xor_sync(0xffffffffu, lt0, 2);
        lt1 += __shfl_xor_sync(0xffffffffu, lt1, 1);
        lt1 += __shfl_xor_sync(0xffffffffu, lt1, 2);
        li0 = li0 * fac0 + lt0;
        li1 = li1 * fac1 + lt1;

#pragma unroll
        for (int ni = 0; ni < 8; ni++) {
            o[ni][0] *= fac0; o[ni][1] *= fac0;
            o[ni][2] *= fac1; o[ni][3] *= fac1;
        }

        // ---- O += P @ V : A-frags directly from score registers
#pragma unroll
        for (int ks = 0; ks < 8; ks++) {
            uint32_t af[4];
            af[0] = f2tf32(c[ks][0]);
            af[1] = f2tf32(c[ks][2]);
            af[2] = f2tf32(c[ks][1]);
            af[3] = f2tf32(c[ks][3]);
            const int kkp = ks * 8 + 2 * tig;
            uint32_t bf[8][2];
#pragma unroll
            for (int ni = 0; ni < 8; ni++) {
                float2 bb = *(const float2*)&Vt[(ni * 8 + g) * KP + kkp];
                bf[ni][0] = __float_as_uint(bb.x);
                bf[ni][1] = __float_as_uint(bb.y);
            }
#pragma unroll
            for (int ni = 0; ni < 8; ni++)
                mma8(o[ni], af, bf[ni][0], bf[ni][1]);
        }
    }

    // ---- normalize + write merged-heads context (tf32-rounded)
    const float inv0 = 1.f / li0;
    const float inv1 = 1.f / li1;
    const size_t row0 = (size_t)b * S + q0 + m0 + g;
#pragma unroll
    for (int ni = 0; ni < 8; ni++) {
        const int col = h * D + ni * 8 + 2 * tig;
        float2 v0, v1;
        v0.x = f2tf32f(o[ni][0] * inv0); v0.y = f2tf32f(o[ni][1] * inv0);
        v1.x = f2tf32f(o[ni][2] * inv1); v1.y = f2tf32f(o[ni][3] * inv1);
        *(float2*)(ctx + row0 * NX + col)       = v0;
        *(float2*)(ctx + (row0 + 8) * NX + col) = v1;
    }
}

// ---------------------------------------------------------------------------
// Launch
// ---------------------------------------------------------------------------
extern "C" void kernel_launch(void* const* d_in, const int* in_sizes, int n_in,
                              void* d_out, int out_size)
{
    const float* x        = (const float*)d_in[0];
    const float* mask     = (const float*)d_in[1];
    const float* c_attn_w = (const float*)d_in[2];
    const float* c_attn_b = (const float*)d_in[3];
    const float* c_proj_w = (const float*)d_in[4];
    const float* c_proj_b = (const float*)d_in[5];
    float* out = (float*)d_out;

    float *qkv, *ctx, *xc, *wt1, *wt2, *kc, *vt;
    cudaGetSymbolAddress((void**)&qkv, g_qkv);
    cudaGetSymbolAddress((void**)&ctx, g_ctx);
    cudaGetSymbolAddress((void**)&xc,  g_xc);
    cudaGetSymbolAddress((void**)&wt1, g_wt1);
    cudaGetSymbolAddress((void**)&wt2, g_wt2);
    cudaGetSymbolAddress((void**)&kc,  g_kc);
    cudaGetSymbolAddress((void**)&vt,  g_vt);

    // 0) Pre-convert / pre-transpose
    cvt_tf32<<<M_TOT * NX / (256 * 4), 256>>>(x, xc);
    transpose_cvt<<<dim3(3 * NX / 32, NX / 32), dim3(32, 8)>>>(c_attn_w, wt1, NX, 3 * NX);
    transpose_cvt<<<dim3(NX / 32, NX / 32),     dim3(32, 8)>>>(c_proj_w, wt2, NX, NX);

    const int gsm_bytes = 4 * 128 * GLD * (int)sizeof(float);   // 73728
    cudaFuncSetAttribute(gemm_mma, cudaFuncAttributeMaxDynamicSharedMemorySize, gsm_bytes);

    // 1) QKV projection (double-buffered)
    gemm_mma<<<dim3(3 * NX / 128, M_TOT / 128), 256, gsm_bytes>>>(
        xc, wt1, c_attn_b, qkv, M_TOT, 3 * NX, NX);

    // 1.5) Prep K/V
    prep_kv<<<dim3(S / 64, 64), 256>>>(qkv, kc, vt);

    // 2) Flash attention (TQ=128, register-resident P)
    {
        const int smem = (128 * PP + 2 * 64 * KP + 64) * (int)sizeof(float); // 71936
        cudaFuncSetAttribute(flash_attn_mma, cudaFuncAttributeMaxDynamicSharedMemorySize, smem);
        dim3 grid(S / 128, B * H);
        flash_attn_mma<<<grid, 256, smem>>>(qkv, kc, vt, mask, ctx);
    }

    // 3) Output projection (double-buffered)
    gemm_mma<<<dim3(NX / 128, M_TOT / 128), 256, gsm_bytes>>>(
        ctx, wt2, c_proj_b, out, M_TOT, NX, NX);
}

// round 12
// speedup vs baseline: 1.2700x; 1.2700x over previous
#include <cuda_runtime.h>
#include <cuda_fp16.h>
#include <math_constants.h>
#include <cstdint>

// Problem constants
#define B   4
#define S   2048
#define NX  1024
#define H   16
#define D   64
#define M_TOT (B * S)   // 8192

// ---------------------------------------------------------------------------
// Global scratch (uint32 units; halves live inside)
// GEMM tiles: [blk128][kblk32][128 rows][40 halves] (20 words/row)
// Flash tiles: [bh][kt][64 rows][72 halves] (36 words/row)
// ---------------------------------------------------------------------------
__device__ float    g_qkv[(size_t)M_TOT * 3 * NX];          // fp32 QKV
__device__ uint32_t g_xh [(size_t)64 * 32 * 128 * 20];      // x fp16 tiles
__device__ uint32_t g_w1h[(size_t)24 * 32 * 128 * 20];      // attn_w^T fp16 tiles
__device__ uint32_t g_w2h[(size_t)8  * 32 * 128 * 20];      // proj_w^T fp16 tiles
__device__ uint32_t g_cxh[(size_t)64 * 32 * 128 * 20];      // ctx fp16 tiles
__device__ uint32_t g_kh [(size_t)64 * 32 * 64 * 36];       // K fp16 tiles [key][d]
__device__ uint32_t g_vh [(size_t)64 * 32 * 64 * 36];       // V^T fp16 tiles [d][key]

// ---------------------------------------------------------------------------
// Helpers
// ---------------------------------------------------------------------------
__device__ __forceinline__ uint32_t pack2(float lo, float hi) {
    __half2 h = __floats2half2_rn(lo, hi);
    return *(uint32_t*)&h;
}

// mma.sync m16n8k16 f16: D = A*B + D (fp32 accum)
__device__ __forceinline__ void mma16(float* c, const uint32_t* a,
                                      uint32_t b0, uint32_t b1) {
    asm volatile(
        "mma.sync.aligned.m16n8k16.row.col.f32.f16.f16.f32 "
        "{%0,%1,%2,%3}, {%4,%5,%6,%7}, {%8,%9}, {%0,%1,%2,%3};"
        : "+f"(c[0]), "+f"(c[1]), "+f"(c[2]), "+f"(c[3])
        : "r"(a[0]), "r"(a[1]), "r"(a[2]), "r"(a[3]), "r"(b0), "r"(b1));
}

// ---------------------------------------------------------------------------
// prep_x: x fp32 -> fp16 padded tiles. grid (K/32, M/128), 256 thr.
// ---------------------------------------------------------------------------
__global__ __launch_bounds__(256)
void prep_x(const float* __restrict__ x, uint32_t* __restrict__ xh,
            int K, int KB)
{
    const int kblk = blockIdx.x, mblk = blockIdx.y;
    const int tid = threadIdx.x;
    const size_t tile = ((size_t)mblk * KB + kblk) * 128 * 20;
    for (int idx = tid; idx < 128 * 8; idx += 256) {
        const int r = idx >> 3, ve = idx & 7;
        float4 v = *(const float4*)(x + (size_t)(mblk * 128 + r) * K + kblk * 32 + ve * 4);
        uint2 o;
        o.x = pack2(v.x, v.y);
        o.y = pack2(v.z, v.w);
        *(uint2*)&xh[tile + r * 20 + ve * 2] = o;
    }
}

// ---------------------------------------------------------------------------
// transpose_h: W[k][n] fp32 -> Wt fp16 tiles [nblk][kblk][128][40h].
// grid (N/32, K/32), block (32, 8).
// ---------------------------------------------------------------------------
__global__ void transpose_h(const float* __restrict__ W, uint32_t* __restrict__ Wt,
                            int K, int N, int KB)
{
    __shared__ float t[32][33];
    const int k0 = blockIdx.y * 32, n0 = blockIdx.x * 32;
    const int x = threadIdx.x, y = threadIdx.y;
#pragma unroll
    for (int i = 0; i < 32; i += 8)
        t[y + i][x] = W[(size_t)(k0 + y + i) * N + n0 + x];
    __syncthreads();
    __half* out = (__half*)Wt;
#pragma unroll
    for (int i = 0; i < 32; i += 8) {
        const int n = n0 + y + i, k = k0 + x;
        const size_t idx = (((size_t)(n >> 7) * KB + (k >> 5)) * 128 + (n & 127)) * 40 + (k & 31);
        out[idx] = __float2half_rn(t[x][y + i]);
    }
}

// ---------------------------------------------------------------------------
// prep_kv: qkv fp32 -> K tiles [key][d] fp16 and V^T tiles [d][key] fp16.
// grid (S/64, B*H), 256 thr.
// ---------------------------------------------------------------------------
__global__ __launch_bounds__(256)
void prep_kv(const float* __restrict__ qkv, uint32_t* __restrict__ kh,
             uint32_t* __restrict__ vh)
{
    __shared__ float vs[64][65];
    const int bh = blockIdx.y;
    const int b = bh >> 4, h = bh & 15;
    const int kt = blockIdx.x;
    const int s0 = kt * 64;
    const int tid = threadIdx.x;

    const float* kbase = qkv + (size_t)b * S * (3 * NX) + NX + h * D;
    const float* vbase = qkv + (size_t)b * S * (3 * NX) + 2 * NX + h * D;
    const size_t tile = ((size_t)bh * 32 + kt) * 64 * 36;

    for (int idx = tid; idx < 64 * 16; idx += 256) {
        const int r  = idx >> 4;
        const int ve = idx & 15;
        const size_t grow = (size_t)(s0 + r) * (3 * NX) + ve * 4;
        float4 kv = *(const float4*)(kbase + grow);
        uint2 ko;
        ko.x = pack2(kv.x, kv.y);
        ko.y = pack2(kv.z, kv.w);
        *(uint2*)&kh[tile + r * 36 + ve * 2] = ko;
        float4 vv = *(const float4*)(vbase + grow);
        vs[4 * ve + 0][r] = vv.x;
        vs[4 * ve + 1][r] = vv.y;
        vs[4 * ve + 2][r] = vv.z;
        vs[4 * ve + 3][r] = vv.w;
    }
    __syncthreads();

    for (int idx = tid; idx < 64 * 16; idx += 256) {
        const int d  = idx >> 4;
        const int ve = idx & 15;
        uint2 vo;
        vo.x = pack2(vs[d][4 * ve + 0], vs[d][4 * ve + 1]);
        vo.y = pack2(vs[d][4 * ve + 2], vs[d][4 * ve + 3]);
        *(uint2*)&vh[tile + d * 36 + ve * 2] = vo;
    }
}

// ---------------------------------------------------------------------------
// fp16 mma GEMM on padded tiles: C[M,N] = A @ Bt^T + bias
// Block 128x128, K-tile 32, 256 threads, warp tile 64x32.
// Staging = linear uint4 copy (coalesced, conflict-free).
// ---------------------------------------------------------------------------
__global__ __launch_bounds__(256)
void gemm_h(const uint32_t* __restrict__ At, const uint32_t* __restrict__ Bt,
            const float* __restrict__ bias, float* __restrict__ C,
            int N, int KB)
{
    __shared__ uint32_t Asw[128 * 20];
    __shared__ uint32_t Bsw[128 * 20];

    const int tid  = threadIdx.x;
    const int wid  = tid >> 5;
    const int lane = tid & 31;
    const int g    = lane >> 2;
    const int tig  = lane & 3;

    const int nblk = blockIdx.x, mblk = blockIdx.y;
    const int wm = (wid >> 2) * 64;
    const int wn = (wid & 3) * 32;

    float c[4][4][4];
#pragma unroll
    for (int mi = 0; mi < 4; mi++)
#pragma unroll
        for (int ni = 0; ni < 4; ni++)
#pragma unroll
            for (int j = 0; j < 4; j++) c[mi][ni][j] = 0.f;

    for (int kc = 0; kc < KB; kc++) {
        __syncthreads();
        const uint4* asrc = (const uint4*)(At + ((size_t)mblk * KB + kc) * 2560);
        const uint4* bsrc = (const uint4*)(Bt + ((size_t)nblk * KB + kc) * 2560);
        // 640 uint4 each; 1280 total over 256 threads = 5 iters
        for (int i = tid; i < 1280; i += 256) {
            if (i < 640) ((uint4*)Asw)[i] = asrc[i];
            else         ((uint4*)Bsw)[i - 640] = bsrc[i - 640];
        }
        __syncthreads();

#pragma unroll
        for (int s = 0; s < 2; s++) {
            const int kk = s * 8 + tig;
            uint32_t af[4][4], bf[4][2];
#pragma unroll
            for (int mi = 0; mi < 4; mi++) {
                const int r = wm + mi * 16;
                af[mi][0] = Asw[(r + g) * 20 + kk];
                af[mi][1] = Asw[(r + g + 8) * 20 + kk];
                af[mi][2] = Asw[(r + g) * 20 + kk + 4];
                af[mi][3] = Asw[(r + g + 8) * 20 + kk + 4];
            }
#pragma unroll
            for (int ni = 0; ni < 4; ni++) {
                const int r = wn + ni * 8;
                bf[ni][0] = Bsw[(r + g) * 20 + kk];
                bf[ni][1] = Bsw[(r + g) * 20 + kk + 4];
            }
#pragma unroll
            for (int mi = 0; mi < 4; mi++)
#pragma unroll
                for (int ni = 0; ni < 4; ni++)
                    mma16(c[mi][ni], af[mi], bf[ni][0], bf[ni][1]);
        }
    }

#pragma unroll
    for (int mi = 0; mi < 4; mi++) {
        const int row0 = mblk * 128 + wm + mi * 16 + g;
#pragma unroll
        for (int ni = 0; ni < 4; ni++) {
            const int col = nblk * 128 + wn + ni * 8 + 2 * tig;
            float2 bb = *(const float2*)(bias + col);
            float2 v0, v1;
            v0.x = c[mi][ni][0] + bb.x; v0.y = c[mi][ni][1] + bb.y;
            v1.x = c[mi][ni][2] + bb.x; v1.y = c[mi][ni][3] + bb.y;
            *(float2*)(C + (size_t)row0 * N + col) = v0;
            *(float2*)(C + (size_t)(row0 + 8) * N + col) = v1;
        }
    }
}

// ---------------------------------------------------------------------------
// Flash attention fp16: 4 warps, TQ=64, TK=64, 4 CTAs/SM.
// K/V staged via linear uint4 copy of pre-padded tiles; P register-resident
// (packed from score regs); output written as fp16 tiles for proj GEMM.
// ---------------------------------------------------------------------------
__global__ void __launch_bounds__(128, 4)
flash_attn_h(const float* __restrict__ qkv, const uint32_t* __restrict__ kh,
             const uint32_t* __restrict__ vh, const float* __restrict__ mask,
             uint32_t* __restrict__ cxh)
{
    __shared__ uint32_t Qsw[64 * 36];
    __shared__ uint32_t Ksw[64 * 36];
    __shared__ uint32_t Vsw[64 * 36];
    __shared__ float    mk[64];

    const int bh = blockIdx.y;
    const int b  = bh >> 4;
    const int h  = bh & 15;
    const int q0 = blockIdx.x * 64;

    const int tid  = threadIdx.x;
    const int wid  = tid >> 5;
    const int lane = tid & 31;
    const int g    = lane >> 2;
    const int tig  = lane & 3;
    const int m0   = wid * 16;

    // Stage Q fp32 -> fp16 smem
    const float* qptr = qkv + (size_t)b * S * (3 * NX) + (size_t)h * D;
    for (int idx = tid; idx < 64 * 16; idx += 128) {
        const int r  = idx >> 4;
        const int ve = idx & 15;
        float4 qa = *(const float4*)(qptr + (size_t)(q0 + r) * (3 * NX) + ve * 4);
        uint2 o;
        o.x = pack2(qa.x, qa.y);
        o.y = pack2(qa.z, qa.w);
        *(uint2*)&Qsw[r * 36 + ve * 2] = o;
    }
    __syncthreads();

    uint32_t aq[4][4];
#pragma unroll
    for (int s = 0; s < 4; s++) {
        const int kk = s * 8 + tig;
        aq[s][0] = Qsw[(m0 + g) * 36 + kk];
        aq[s][1] = Qsw[(m0 + g + 8) * 36 + kk];
        aq[s][2] = Qsw[(m0 + g) * 36 + kk + 4];
        aq[s][3] = Qsw[(m0 + g + 8) * 36 + kk + 4];
    }

    float mi0 = -CUDART_INF_F, mi1 = -CUDART_INF_F;
    float li0 = 0.f, li1 = 0.f;
    float o[8][4];
#pragma unroll
    for (int ni = 0; ni < 8; ni++)
#pragma unroll
        for (int j = 0; j < 4; j++) o[ni][j] = 0.f;

    for (int kt = 0; kt < 32; kt++) {
        __syncthreads();
        const uint4* ksrc = (const uint4*)(kh + ((size_t)bh * 32 + kt) * 2304);
        const uint4* vsrc = (const uint4*)(vh + ((size_t)bh * 32 + kt) * 2304);
        // 576 uint4 each, 1152 total / 128 thr = 9 iters
        for (int i = tid; i < 1152; i += 128) {
            if (i < 576) ((uint4*)Ksw)[i] = ksrc[i];
            else         ((uint4*)Vsw)[i - 576] = vsrc[i - 576];
        }
        if (tid < 16)
            *(float4*)&mk[tid * 4] = *(const float4*)&mask[(size_t)b * S + kt * 64 + tid * 4];
        __syncthreads();

        // ---- QK^T (4 k16 steps over D=64)
        float c[8][4];
#pragma unroll
        for (int ni = 0; ni < 8; ni++)
#pragma unroll
            for (int j = 0; j < 4; j++) c[ni][j] = 0.f;

#pragma unroll
        for (int s = 0; s < 4; s++) {
            const int kk = s * 8 + tig;
            uint32_t bf[8][2];
#pragma unroll
            for (int ni = 0; ni < 8; ni++) {
                bf[ni][0] = Ksw[(ni * 8 + g) * 36 + kk];
                bf[ni][1] = Ksw[(ni * 8 + g) * 36 + kk + 4];
            }
#pragma unroll
            for (int ni = 0; ni < 8; ni++)
                mma16(c[ni], aq[s], bf[ni][0], bf[ni][1]);
        }

        // ---- scale + mask
#pragma unroll
        for (int ni = 0; ni < 8; ni++) {
            float2 mm = *(const float2*)&mk[ni * 8 + 2 * tig];
            c[ni][0] = fmaf(c[ni][0], 0.125f, mm.x);
            c[ni][1] = fmaf(c[ni][1], 0.125f, mm.y);
            c[ni][2] = fmaf(c[ni][2], 0.125f, mm.x);
            c[ni][3] = fmaf(c[ni][3], 0.125f, mm.y);
        }

        // ---- online softmax
        float mt0 = -CUDART_INF_F, mt1 = -CUDART_INF_F;
#pragma unroll
        for (int ni = 0; ni < 8; ni++) {
            mt0 = fmaxf(mt0, fmaxf(c[ni][0], c[ni][1]));
            mt1 = fmaxf(mt1, fmaxf(c[ni][2], c[ni][3]));
        }
        mt0 = fmaxf(mt0, __shfl_xor_sync(0xffffffffu, mt0, 1));
        mt0 = fmaxf(mt0, __shfl_xor_sync(0xffffffffu, mt0, 2));
        mt1 = fmaxf(mt1, __shfl_xor_sync(0xffffffffu, mt1, 1));
        mt1 = fmaxf(mt1, __shfl_xor_sync(0xffffffffu, mt1, 2));

        const float mn0 = fmaxf(mi0, mt0);
        const float mn1 = fmaxf(mi1, mt1);
        const float fac0 = __expf(mi0 - mn0);
        const float fac1 = __expf(mi1 - mn1);
        mi0 = mn0; mi1 = mn1;

        float lt0 = 0.f, lt1 = 0.f;
#pragma unroll
        for (int ni = 0; ni < 8; ni++) {
            c[ni][0] = __expf(c[ni][0] - mn0);
            c[ni][1] = __expf(c[ni][1] - mn0);
            c[ni][2] = __expf(c[ni][2] - mn1);
            c[ni][3] = __expf(c[ni][3] - mn1);
            lt0 += c[ni][0] + c[ni][1];
            lt1 += c[ni][2] + c[ni][3];
        }
        lt0 += __shfl_xor_sync(0xffffffffu, lt0, 1);
        lt0 += __shfl_xor_sync(0xffffffffu, lt0, 2);
        lt1 += __shfl_xor_sync(0xffffffffu, lt1, 1);
        lt1 += __shfl_xor_sync(0xffffffffu, lt1, 2);
        li0 = li0 * fac0 + lt0;
        li1 = li1 * fac1 + lt1;

#pragma unroll
        for (int ni = 0; ni < 8; ni++) {
            o[ni][0] *= fac0; o[ni][1] *= fac0;
            o[ni][2] *= fac1; o[ni][3] *= fac1;
        }

        // ---- O += P @ V : P packed directly from score regs (4 k16 steps)
#pragma unroll
        for (int m = 0; m < 4; m++) {
            uint32_t af[4];
            af[0] = pack2(c[2 * m][0],     c[2 * m][1]);      // row g,   keys 16m+2tig,+1
            af[1] = pack2(c[2 * m][2],     c[2 * m][3]);      // row g+8
            af[2] = pack2(c[2 * m + 1][0], c[2 * m + 1][1]);  // row g,   keys +8
            af[3] = pack2(c[2 * m + 1][2], c[2 * m + 1][3]);  // row g+8
            const int kk = m * 8 + tig;
            uint32_t bf[8][2];
#pragma unroll
            for (int ni = 0; ni < 8; ni++) {
                bf[ni][0] = Vsw[(ni * 8 + g) * 36 + kk];
                bf[ni][1] = Vsw[(ni * 8 + g) * 36 + kk + 4];
            }
#pragma unroll
            for (int ni = 0; ni < 8; ni++)
                mma16(o[ni], af, bf[ni][0], bf[ni][1]);
        }
    }

    // ---- normalize + write ctx as fp16 tiles (proj GEMM A operand)
    const float inv0 = 1.f / li0;
    const float inv1 = 1.f / li1;
    const int row0 = (b << 11) + q0 + m0 + g;       // b*S + ...
#pragma unroll
    for (int ni = 0; ni < 8; ni++) {
        const int col = h * D + ni * 8 + 2 * tig;
        const int kblk = col >> 5, off = col & 31;
        {
            const int mblk = row0 >> 7, r = row0 & 127;
            cxh[(((size_t)mblk * 32 + kblk) * 128 + r) * 20 + (off >> 1)] =
                pack2(o[ni][0] * inv0, o[ni][1] * inv0);
        }
        {
            const int row1 = row0 + 8;
            const int mblk = row1 >> 7, r = row1 & 127;
            cxh[(((size_t)mblk * 32 + kblk) * 128 + r) * 20 + (off >> 1)] =
                pack2(o[ni][2] * inv1, o[ni][3] * inv1);
        }
    }
}

// ---------------------------------------------------------------------------
// Launch
// ---------------------------------------------------------------------------
extern "C" void kernel_launch(void* const* d_in, const int* in_sizes, int n_in,
                              void* d_out, int out_size)
{
    const float* x        = (const float*)d_in[0];
    const float* mask     = (const float*)d_in[1];
    const float* c_attn_w = (const float*)d_in[2];
    const float* c_attn_b = (const float*)d_in[3];
    const float* c_proj_w = (const float*)d_in[4];
    const float* c_proj_b = (const float*)d_in[5];
    float* out = (float*)d_out;

    float* qkv;
    uint32_t *xh, *w1h, *w2h, *cxh, *kh, *vh;
    cudaGetSymbolAddress((void**)&qkv, g_qkv);
    cudaGetSymbolAddress((void**)&xh,  g_xh);
    cudaGetSymbolAddress((void**)&w1h, g_w1h);
    cudaGetSymbolAddress((void**)&w2h, g_w2h);
    cudaGetSymbolAddress((void**)&cxh, g_cxh);
    cudaGetSymbolAddress((void**)&kh,  g_kh);
    cudaGetSymbolAddress((void**)&vh,  g_vh);

    // 0) Pre-convert to fp16 padded tiles
    prep_x<<<dim3(32, 64), 256>>>(x, xh, NX, 32);
    transpose_h<<<dim3(3 * NX / 32, NX / 32), dim3(32, 8)>>>(c_attn_w, w1h, NX, 3 * NX, 32);
    transpose_h<<<dim3(NX / 32, NX / 32),     dim3(32, 8)>>>(c_proj_w, w2h, NX, NX, 32);

    // 1) QKV projection (fp16 mma) -> qkv fp32
    gemm_h<<<dim3(24, 64), 256>>>(xh, w1h, c_attn_b, qkv, 3 * NX, 32);

    // 1.5) Prep K/V fp16 tiles
    prep_kv<<<dim3(32, 64), 256>>>(qkv, kh, vh);

    // 2) Flash attention -> ctx fp16 tiles
    flash_attn_h<<<dim3(32, 64), 128>>>(qkv, kh, vh, mask, cxh);

    // 3) Output projection (fp16 mma) -> out fp32
    gemm_h<<<dim3(8, 64), 256>>>(cxh, w2h, c_proj_b, out, NX, 32);
}

// round 13
// speedup vs baseline: 1.5188x; 1.1959x over previous
#include <cuda_runtime.h>
#include <cuda_fp16.h>
#include <math_constants.h>
#include <cstdint>

// Problem constants
#define B   4
#define S   2048
#define NX  1024
#define H   16
#define D   64
#define M_TOT (B * S)   // 8192

// ---------------------------------------------------------------------------
// Global scratch (uint32 units; halves live inside)
// GEMM tiles: [blk128][kblk32][128 rows][40 halves] (20 words/row)
// Flash tiles: [bh][kt][64 rows][72 halves] (36 words/row)
// ---------------------------------------------------------------------------
__device__ float    g_qkv[(size_t)M_TOT * 3 * NX];          // fp32 QKV
__device__ uint32_t g_xh [(size_t)64 * 32 * 128 * 20];      // x fp16 tiles
__device__ uint32_t g_w1h[(size_t)24 * 32 * 128 * 20];      // attn_w^T fp16 tiles
__device__ uint32_t g_w2h[(size_t)8  * 32 * 128 * 20];      // proj_w^T fp16 tiles
__device__ uint32_t g_cxh[(size_t)64 * 32 * 128 * 20];      // ctx fp16 tiles
__device__ uint32_t g_kh [(size_t)64 * 32 * 64 * 36];       // K fp16 tiles [key][d]
__device__ uint32_t g_vh [(size_t)64 * 32 * 64 * 36];       // V^T fp16 tiles [d][key]

// ---------------------------------------------------------------------------
// Helpers
// ---------------------------------------------------------------------------
__device__ __forceinline__ uint32_t pack2(float lo, float hi) {
    __half2 h = __floats2half2_rn(lo, hi);
    return *(uint32_t*)&h;
}

// mma.sync m16n8k16 f16: D = A*B + D (fp32 accum)
__device__ __forceinline__ void mma16(float* c, const uint32_t* a,
                                      uint32_t b0, uint32_t b1) {
    asm volatile(
        "mma.sync.aligned.m16n8k16.row.col.f32.f16.f16.f32 "
        "{%0,%1,%2,%3}, {%4,%5,%6,%7}, {%8,%9}, {%0,%1,%2,%3};"
        : "+f"(c[0]), "+f"(c[1]), "+f"(c[2]), "+f"(c[3])
        : "r"(a[0]), "r"(a[1]), "r"(a[2]), "r"(a[3]), "r"(b0), "r"(b1));
}

// ---------------------------------------------------------------------------
// prep_x: x fp32 -> fp16 padded tiles. grid (K/32, M/128), 256 thr.
// ---------------------------------------------------------------------------
__global__ __launch_bounds__(256)
void prep_x(const float* __restrict__ x, uint32_t* __restrict__ xh,
            int K, int KB)
{
    const int kblk = blockIdx.x, mblk = blockIdx.y;
    const int tid = threadIdx.x;
    const size_t tile = ((size_t)mblk * KB + kblk) * 128 * 20;
    for (int idx = tid; idx < 128 * 8; idx += 256) {
        const int r = idx >> 3, ve = idx & 7;
        float4 v = *(const float4*)(x + (size_t)(mblk * 128 + r) * K + kblk * 32 + ve * 4);
        uint2 o;
        o.x = pack2(v.x, v.y);
        o.y = pack2(v.z, v.w);
        *(uint2*)&xh[tile + r * 20 + ve * 2] = o;
    }
}

// ---------------------------------------------------------------------------
// transpose_h: W[k][n] fp32 -> Wt fp16 tiles [nblk][kblk][128][40h].
// grid (N/32, K/32), block (32, 8).
// ---------------------------------------------------------------------------
__global__ void transpose_h(const float* __restrict__ W, uint32_t* __restrict__ Wt,
                            int K, int N, int KB)
{
    __shared__ float t[32][33];
    const int k0 = blockIdx.y * 32, n0 = blockIdx.x * 32;
    const int x = threadIdx.x, y = threadIdx.y;
#pragma unroll
    for (int i = 0; i < 32; i += 8)
        t[y + i][x] = W[(size_t)(k0 + y + i) * N + n0 + x];
    __syncthreads();
    __half* out = (__half*)Wt;
#pragma unroll
    for (int i = 0; i < 32; i += 8) {
        const int n = n0 + y + i, k = k0 + x;
        const size_t idx = (((size_t)(n >> 7) * KB + (k >> 5)) * 128 + (n & 127)) * 40 + (k & 31);
        out[idx] = __float2half_rn(t[x][y + i]);
    }
}

// ---------------------------------------------------------------------------
// prep_kv: qkv fp32 -> K tiles [key][d] fp16 and V^T tiles [d][key] fp16.
// grid (S/64, B*H), 256 thr.
// ---------------------------------------------------------------------------
__global__ __launch_bounds__(256)
void prep_kv(const float* __restrict__ qkv, uint32_t* __restrict__ kh,
             uint32_t* __restrict__ vh)
{
    __shared__ float vs[64][65];
    const int bh = blockIdx.y;
    const int b = bh >> 4, h = bh & 15;
    const int kt = blockIdx.x;
    const int s0 = kt * 64;
    const int tid = threadIdx.x;

    const float* kbase = qkv + (size_t)b * S * (3 * NX) + NX + h * D;
    const float* vbase = qkv + (size_t)b * S * (3 * NX) + 2 * NX + h * D;
    const size_t tile = ((size_t)bh * 32 + kt) * 64 * 36;

    for (int idx = tid; idx < 64 * 16; idx += 256) {
        const int r  = idx >> 4;
        const int ve = idx & 15;
        const size_t grow = (size_t)(s0 + r) * (3 * NX) + ve * 4;
        float4 kv = *(const float4*)(kbase + grow);
        uint2 ko;
        ko.x = pack2(kv.x, kv.y);
        ko.y = pack2(kv.z, kv.w);
        *(uint2*)&kh[tile + r * 36 + ve * 2] = ko;
        float4 vv = *(const float4*)(vbase + grow);
        vs[4 * ve + 0][r] = vv.x;
        vs[4 * ve + 1][r] = vv.y;
        vs[4 * ve + 2][r] = vv.z;
        vs[4 * ve + 3][r] = vv.w;
    }
    __syncthreads();

    for (int idx = tid; idx < 64 * 16; idx += 256) {
        const int d  = idx >> 4;
        const int ve = idx & 15;
        uint2 vo;
        vo.x = pack2(vs[d][4 * ve + 0], vs[d][4 * ve + 1]);
        vo.y = pack2(vs[d][4 * ve + 2], vs[d][4 * ve + 3]);
        *(uint2*)&vh[tile + d * 36 + ve * 2] = vo;
    }
}

// ---------------------------------------------------------------------------
// fp16 mma GEMM on padded tiles: C[M,N] = A @ Bt^T + bias
// Block 128x128, K-tile 64 (two k-blocks per staging round), 256 threads,
// warp tile 64x32. Staging = linear uint4 copy (coalesced, conflict-free).
// ---------------------------------------------------------------------------
__global__ __launch_bounds__(256)
void gemm_h(const uint32_t* __restrict__ At, const uint32_t* __restrict__ Bt,
            const float* __restrict__ bias, float* __restrict__ C,
            int N, int KB)
{
    __shared__ uint32_t Asw[2 * 128 * 20];   // two k-blocks
    __shared__ uint32_t Bsw[2 * 128 * 20];

    const int tid  = threadIdx.x;
    const int wid  = tid >> 5;
    const int lane = tid & 31;
    const int g    = lane >> 2;
    const int tig  = lane & 3;

    const int nblk = blockIdx.x, mblk = blockIdx.y;
    const int wm = (wid >> 2) * 64;
    const int wn = (wid & 3) * 32;

    float c[4][4][4];
#pragma unroll
    for (int mi = 0; mi < 4; mi++)
#pragma unroll
        for (int ni = 0; ni < 4; ni++)
#pragma unroll
            for (int j = 0; j < 4; j++) c[mi][ni][j] = 0.f;

    const int KB2 = KB >> 1;
    for (int kc = 0; kc < KB2; kc++) {
        __syncthreads();
        // Two consecutive k-blocks are contiguous: 5120 words = 1280 uint4 each
        const uint4* asrc = (const uint4*)(At + ((size_t)mblk * KB + 2 * kc) * 2560);
        const uint4* bsrc = (const uint4*)(Bt + ((size_t)nblk * KB + 2 * kc) * 2560);
        for (int i = tid; i < 2560; i += 256) {
            if (i < 1280) ((uint4*)Asw)[i] = asrc[i];
            else          ((uint4*)Bsw)[i - 1280] = bsrc[i - 1280];
        }
        __syncthreads();

#pragma unroll
        for (int kb = 0; kb < 2; kb++) {
            const uint32_t* Ab = Asw + kb * 2560;
            const uint32_t* Bb = Bsw + kb * 2560;
#pragma unroll
            for (int s = 0; s < 2; s++) {
                const int kk = s * 8 + tig;
                uint32_t af[4][4], bf[4][2];
#pragma unroll
                for (int mi = 0; mi < 4; mi++) {
                    const int r = wm + mi * 16;
                    af[mi][0] = Ab[(r + g) * 20 + kk];
                    af[mi][1] = Ab[(r + g + 8) * 20 + kk];
                    af[mi][2] = Ab[(r + g) * 20 + kk + 4];
                    af[mi][3] = Ab[(r + g + 8) * 20 + kk + 4];
                }
#pragma unroll
                for (int ni = 0; ni < 4; ni++) {
                    const int r = wn + ni * 8;
                    bf[ni][0] = Bb[(r + g) * 20 + kk];
                    bf[ni][1] = Bb[(r + g) * 20 + kk + 4];
                }
#pragma unroll
                for (int mi = 0; mi < 4; mi++)
#pragma unroll
                    for (int ni = 0; ni < 4; ni++)
                        mma16(c[mi][ni], af[mi], bf[ni][0], bf[ni][1]);
            }
        }
    }

#pragma unroll
    for (int mi = 0; mi < 4; mi++) {
        const int row0 = mblk * 128 + wm + mi * 16 + g;
#pragma unroll
        for (int ni = 0; ni < 4; ni++) {
            const int col = nblk * 128 + wn + ni * 8 + 2 * tig;
            float2 bb = *(const float2*)(bias + col);
            float2 v0, v1;
            v0.x = c[mi][ni][0] + bb.x; v0.y = c[mi][ni][1] + bb.y;
            v1.x = c[mi][ni][2] + bb.x; v1.y = c[mi][ni][3] + bb.y;
            *(float2*)(C + (size_t)row0 * N + col) = v0;
            *(float2*)(C + (size_t)(row0 + 8) * N + col) = v1;
        }
    }
}

// ---------------------------------------------------------------------------
// Flash attention fp16: 4 warps, TQ=64, TK=64, 4 CTAs/SM.
// K/V staged via linear uint4 copy of pre-padded tiles; P register-resident
// (packed from score regs); output written as fp16 tiles for proj GEMM.
// ---------------------------------------------------------------------------
__global__ void __launch_bounds__(128, 4)
flash_attn_h(const float* __restrict__ qkv, const uint32_t* __restrict__ kh,
             const uint32_t* __restrict__ vh, const float* __restrict__ mask,
             uint32_t* __restrict__ cxh)
{
    __shared__ uint32_t Qsw[64 * 36];
    __shared__ uint32_t Ksw[64 * 36];
    __shared__ uint32_t Vsw[64 * 36];
    __shared__ float    mk[64];

    const int bh = blockIdx.y;
    const int b  = bh >> 4;
    const int h  = bh & 15;
    const int q0 = blockIdx.x * 64;

    const int tid  = threadIdx.x;
    const int wid  = tid >> 5;
    const int lane = tid & 31;
    const int g    = lane >> 2;
    const int tig  = lane & 3;
    const int m0   = wid * 16;

    // Stage Q fp32 -> fp16 smem
    const float* qptr = qkv + (size_t)b * S * (3 * NX) + (size_t)h * D;
    for (int idx = tid; idx < 64 * 16; idx += 128) {
        const int r  = idx >> 4;
        const int ve = idx & 15;
        float4 qa = *(const float4*)(qptr + (size_t)(q0 + r) * (3 * NX) + ve * 4);
        uint2 o;
        o.x = pack2(qa.x, qa.y);
        o.y = pack2(qa.z, qa.w);
        *(uint2*)&Qsw[r * 36 + ve * 2] = o;
    }
    __syncthreads();

    uint32_t aq[4][4];
#pragma unroll
    for (int s = 0; s < 4; s++) {
        const int kk = s * 8 + tig;
        aq[s][0] = Qsw[(m0 + g) * 36 + kk];
        aq[s][1] = Qsw[(m0 + g + 8) * 36 + kk];
        aq[s][2] = Qsw[(m0 + g) * 36 + kk + 4];
        aq[s][3] = Qsw[(m0 + g + 8) * 36 + kk + 4];
    }

    float mi0 = -CUDART_INF_F, mi1 = -CUDART_INF_F;
    float li0 = 0.f, li1 = 0.f;
    float o[8][4];
#pragma unroll
    for (int ni = 0; ni < 8; ni++)
#pragma unroll
        for (int j = 0; j < 4; j++) o[ni][j] = 0.f;

    for (int kt = 0; kt < 32; kt++) {
        __syncthreads();
        const uint4* ksrc = (const uint4*)(kh + ((size_t)bh * 32 + kt) * 2304);
        const uint4* vsrc = (const uint4*)(vh + ((size_t)bh * 32 + kt) * 2304);
        for (int i = tid; i < 1152; i += 128) {
            if (i < 576) ((uint4*)Ksw)[i] = ksrc[i];
            else         ((uint4*)Vsw)[i - 576] = vsrc[i - 576];
        }
        if (tid < 16)
            *(float4*)&mk[tid * 4] = *(const float4*)&mask[(size_t)b * S + kt * 64 + tid * 4];
        __syncthreads();

        // ---- QK^T (4 k16 steps over D=64)
        float c[8][4];
#pragma unroll
        for (int ni = 0; ni < 8; ni++)
#pragma unroll
            for (int j = 0; j < 4; j++) c[ni][j] = 0.f;

#pragma unroll
        for (int s = 0; s < 4; s++) {
            const int kk = s * 8 + tig;
            uint32_t bf[8][2];
#pragma unroll
            for (int ni = 0; ni < 8; ni++) {
                bf[ni][0] = Ksw[(ni * 8 + g) * 36 + kk];
                bf[ni][1] = Ksw[(ni * 8 + g) * 36 + kk + 4];
            }
#pragma unroll
            for (int ni = 0; ni < 8; ni++)
                mma16(c[ni], aq[s], bf[ni][0], bf[ni][1]);
        }

        // ---- scale + mask
#pragma unroll
        for (int ni = 0; ni < 8; ni++) {
            float2 mm = *(const float2*)&mk[ni * 8 + 2 * tig];
            c[ni][0] = fmaf(c[ni][0], 0.125f, mm.x);
            c[ni][1] = fmaf(c[ni][1], 0.125f, mm.y);
            c[ni][2] = fmaf(c[ni][2], 0.125f, mm.x);
            c[ni][3] = fmaf(c[ni][3], 0.125f, mm.y);
        }

        // ---- online softmax
        float mt0 = -CUDART_INF_F, mt1 = -CUDART_INF_F;
#pragma unroll
        for (int ni = 0; ni < 8; ni++) {
            mt0 = fmaxf(mt0, fmaxf(c[ni][0], c[ni][1]));
            mt1 = fmaxf(mt1, fmaxf(c[ni][2], c[ni][3]));
        }
        mt0 = fmaxf(mt0, __shfl_xor_sync(0xffffffffu, mt0, 1));
        mt0 = fmaxf(mt0, __shfl_xor_sync(0xffffffffu, mt0, 2));
        mt1 = fmaxf(mt1, __shfl_xor_sync(0xffffffffu, mt1, 1));
        mt1 = fmaxf(mt1, __shfl_xor_sync(0xffffffffu, mt1, 2));

        const float mn0 = fmaxf(mi0, mt0);
        const float mn1 = fmaxf(mi1, mt1);
        const float fac0 = __expf(mi0 - mn0);
        const float fac1 = __expf(mi1 - mn1);
        mi0 = mn0; mi1 = mn1;

        float lt0 = 0.f, lt1 = 0.f;
#pragma unroll
        for (int ni = 0; ni < 8; ni++) {
            c[ni][0] = __expf(c[ni][0] - mn0);
            c[ni][1] = __expf(c[ni][1] - mn0);
            c[ni][2] = __expf(c[ni][2] - mn1);
            c[ni][3] = __expf(c[ni][3] - mn1);
            lt0 += c[ni][0] + c[ni][1];
            lt1 += c[ni][2] + c[ni][3];
        }
        lt0 += __shfl_xor_sync(0xffffffffu, lt0, 1);
        lt0 += __shfl_xor_sync(0xffffffffu, lt0, 2);
        lt1 += __shfl_xor_sync(0xffffffffu, lt1, 1);
        lt1 += __shfl_xor_sync(0xffffffffu, lt1, 2);
        li0 = li0 * fac0 + lt0;
        li1 = li1 * fac1 + lt1;

#pragma unroll
        for (int ni = 0; ni < 8; ni++) {
            o[ni][0] *= fac0; o[ni][1] *= fac0;
            o[ni][2] *= fac1; o[ni][3] *= fac1;
        }

        // ---- O += P @ V : P packed directly from score regs (4 k16 steps)
#pragma unroll
        for (int m = 0; m < 4; m++) {
            uint32_t af[4];
            af[0] = pack2(c[2 * m][0],     c[2 * m][1]);
            af[1] = pack2(c[2 * m][2],     c[2 * m][3]);
            af[2] = pack2(c[2 * m + 1][0], c[2 * m + 1][1]);
            af[3] = pack2(c[2 * m + 1][2], c[2 * m + 1][3]);
            const int kk = m * 8 + tig;
            uint32_t bf[8][2];
#pragma unroll
            for (int ni = 0; ni < 8; ni++) {
                bf[ni][0] = Vsw[(ni * 8 + g) * 36 + kk];
                bf[ni][1] = Vsw[(ni * 8 + g) * 36 + kk + 4];
            }
#pragma unroll
            for (int ni = 0; ni < 8; ni++)
                mma16(o[ni], af, bf[ni][0], bf[ni][1]);
        }
    }

    // ---- normalize + write ctx as fp16 tiles (proj GEMM A operand)
    const float inv0 = 1.f / li0;
    const float inv1 = 1.f / li1;
    const int row0 = (b << 11) + q0 + m0 + g;
#pragma unroll
    for (int ni = 0; ni < 8; ni++) {
        const int col = h * D + ni * 8 + 2 * tig;
        const int kblk = col >> 5, off = col & 31;
        {
            const int mblk = row0 >> 7, r = row0 & 127;
            cxh[(((size_t)mblk * 32 + kblk) * 128 + r) * 20 + (off >> 1)] =
                pack2(o[ni][0] * inv0, o[ni][1] * inv0);
        }
        {
            const int row1 = row0 + 8;
            const int mblk = row1 >> 7, r = row1 & 127;
            cxh[(((size_t)mblk * 32 + kblk) * 128 + r) * 20 + (off >> 1)] =
                pack2(o[ni][2] * inv1, o[ni][3] * inv1);
        }
    }
}

// ---------------------------------------------------------------------------
// Launch
// ---------------------------------------------------------------------------
extern "C" void kernel_launch(void* const* d_in, const int* in_sizes, int n_in,
                              void* d_out, int out_size)
{
    const float* x        = (const float*)d_in[0];
    const float* mask     = (const float*)d_in[1];
    const float* c_attn_w = (const float*)d_in[2];
    const float* c_attn_b = (const float*)d_in[3];
    const float* c_proj_w = (const float*)d_in[4];
    const float* c_proj_b = (const float*)d_in[5];
    float* out = (float*)d_out;

    float* qkv;
    uint32_t *xh, *w1h, *w2h, *cxh, *kh, *vh;
    cudaGetSymbolAddress((void**)&qkv, g_qkv);
    cudaGetSymbolAddress((void**)&xh,  g_xh);
    cudaGetSymbolAddress((void**)&w1h, g_w1h);
    cudaGetSymbolAddress((void**)&w2h, g_w2h);
    cudaGetSymbolAddress((void**)&cxh, g_cxh);
    cudaGetSymbolAddress((void**)&kh,  g_kh);
    cudaGetSymbolAddress((void**)&vh,  g_vh);

    // 0) Pre-convert to fp16 padded tiles
    prep_x<<<dim3(32, 64), 256>>>(x, xh, NX, 32);
    transpose_h<<<dim3(3 * NX / 32, NX / 32), dim3(32, 8)>>>(c_attn_w, w1h, NX, 3 * NX, 32);
    transpose_h<<<dim3(NX / 32, NX / 32),     dim3(32, 8)>>>(c_proj_w, w2h, NX, NX, 32);

    // 1) QKV projection (fp16 mma, K-tile 64) -> qkv fp32
    gemm_h<<<dim3(24, 64), 256>>>(xh, w1h, c_attn_b, qkv, 3 * NX, 32);

    // 1.5) Prep K/V fp16 tiles
    prep_kv<<<dim3(32, 64), 256>>>(qkv, kh, vh);

    // 2) Flash attention -> ctx fp16 tiles
    flash_attn_h<<<dim3(32, 64), 128>>>(qkv, kh, vh, mask, cxh);

    // 3) Output projection (fp16 mma, K-tile 64) -> out fp32
    gemm_h<<<dim3(8, 64), 256>>>(cxh, w2h, c_proj_b, out, NX, 32);
}